// round 14
// baseline (speedup 1.0000x reference)
#include <cuda_runtime.h>
#include <cstdint>
#include <math.h>

// Problem shapes (fixed by the dataset instance)
#define N_TOK 8192
#define HDIM  1024
#define IDIM  4096

// -------- scratch (static __device__ arrays: allocation-free) --------
__device__ float g_xln[(size_t)N_TOK * HDIM];    //  32 MB (tf32-rounded LN output)
__device__ float g_hid[(size_t)N_TOK * IDIM];    // 128 MB (tf32-rounded GEGLU output)
__device__ float g_y  [(size_t)N_TOK * HDIM];    //  32 MB (gemm2 K-half 0)
__device__ float g_y2 [(size_t)N_TOK * HDIM];    //  32 MB (gemm2 K-half 1)
__device__ float g_w1r[(size_t)2 * IDIM * HDIM]; //  64 MB (tf32-rounded W1)
__device__ float g_w2r[(size_t)HDIM * IDIM];     //  16 MB (tf32-rounded W2)

// ============================= helpers =============================
__device__ __forceinline__ uint32_t f2tf(float f) {
    uint32_t r;
    asm("cvt.rna.tf32.f32 %0, %1;" : "=r"(r) : "f"(f));
    return r;
}
__device__ __forceinline__ float roundtf(float f) { return __uint_as_float(f2tf(f)); }

__device__ __forceinline__ uint32_t smem_u32(const void* p) {
    uint32_t a;
    asm("{ .reg .u64 t; cvta.to.shared.u64 t, %1; cvt.u32.u64 %0, t; }" : "=r"(a) : "l"(p));
    return a;
}
__device__ __forceinline__ void cp_async16(uint32_t smem_addr, const void* gmem) {
    asm volatile("cp.async.cg.shared.global [%0], [%1], 16;\n" :: "r"(smem_addr), "l"(gmem));
}
#define CP_COMMIT() asm volatile("cp.async.commit_group;\n" ::)
#define CP_WAIT2()  asm volatile("cp.async.wait_group 2;\n" ::)
#define CP_WAIT1()  asm volatile("cp.async.wait_group 1;\n" ::)
#define CP_WAIT0()  asm volatile("cp.async.wait_group 0;\n" ::)

// ldmatrix x4: four 8x8 b16 tiles == four 8x4 tf32 tiles
__device__ __forceinline__ void ldsm4(uint32_t r[4], uint32_t addr) {
    asm volatile("ldmatrix.sync.aligned.m8n8.x4.shared.b16 {%0,%1,%2,%3}, [%4];"
                 : "=r"(r[0]), "=r"(r[1]), "=r"(r[2]), "=r"(r[3]) : "r"(addr));
}

__device__ __forceinline__ void mma_tf32(float c[4], const uint32_t a[4], const uint32_t b0,
                                         const uint32_t b1) {
    asm volatile(
        "mma.sync.aligned.m16n8k8.row.col.f32.tf32.tf32.f32 "
        "{%0,%1,%2,%3}, {%4,%5,%6,%7}, {%8,%9}, {%0,%1,%2,%3};"
        : "+f"(c[0]), "+f"(c[1]), "+f"(c[2]), "+f"(c[3])
        : "r"(a[0]), "r"(a[1]), "r"(a[2]), "r"(a[3]), "r"(b0), "r"(b1));
}

__device__ __forceinline__ float gelu_tanh(float v) {
    const float c0 = 0.7978845608028654f;
    const float c1 = 0.044715f;
    float u = c0 * (v + c1 * v * v * v);
    return 0.5f * v * (1.0f + tanhf(u));
}

// ============================ tiny kernels ============================
__global__ void round_tf32_kernel(const float* __restrict__ in,
                                  float* __restrict__ outp, int n4) {
    int i = blockIdx.x * blockDim.x + threadIdx.x;
    if (i < n4) {
        float4 v = ((const float4*)in)[i];
        v.x = roundtf(v.x); v.y = roundtf(v.y);
        v.z = roundtf(v.z); v.w = roundtf(v.w);
        ((float4*)outp)[i] = v;
    }
}

__global__ void ln_pre_kernel(const float* __restrict__ x,
                              const float* __restrict__ w,
                              const float* __restrict__ b) {
    int row = blockIdx.x;
    int t = threadIdx.x;
    const float4* xr = (const float4*)(x + (size_t)row * HDIM);
    float4 f = xr[t];
    float s  = f.x + f.y + f.z + f.w;
    float sq = f.x*f.x + f.y*f.y + f.z*f.z + f.w*f.w;
    #pragma unroll
    for (int o = 16; o; o >>= 1) {
        s  += __shfl_xor_sync(0xffffffffu, s,  o);
        sq += __shfl_xor_sync(0xffffffffu, sq, o);
    }
    __shared__ float ss[8], ssq[8];
    int wid = t >> 5, lid = t & 31;
    if (lid == 0) { ss[wid] = s; ssq[wid] = sq; }
    __syncthreads();
    if (wid == 0) {
        s  = (lid < 8) ? ss[lid]  : 0.0f;
        sq = (lid < 8) ? ssq[lid] : 0.0f;
        #pragma unroll
        for (int o = 4; o; o >>= 1) {
            s  += __shfl_xor_sync(0xffffffffu, s,  o);
            sq += __shfl_xor_sync(0xffffffffu, sq, o);
        }
        if (lid == 0) { ss[0] = s; ssq[0] = sq; }
    }
    __syncthreads();
    float mu  = ss[0] * (1.0f / HDIM);
    float var = ssq[0] * (1.0f / HDIM) - mu * mu;
    float rs  = rsqrtf(var + 1e-5f);
    float4 wv = ((const float4*)w)[t];
    float4 bv = ((const float4*)b)[t];
    float4 o;
    o.x = roundtf((f.x - mu) * rs * wv.x + bv.x);
    o.y = roundtf((f.y - mu) * rs * wv.y + bv.y);
    o.z = roundtf((f.z - mu) * rs * wv.z + bv.z);
    o.w = roundtf((f.w - mu) * rs * wv.w + bv.w);
    ((float4*)(g_xln + (size_t)row * HDIM))[t] = o;
}

// post-LN: y = ya + yb + b2 (split-K reduce + bias), then LN + residual.
__global__ void ln_post_kernel(const float* __restrict__ b2,
                               const float* __restrict__ w,
                               const float* __restrict__ b,
                               const float* __restrict__ x,
                               float* __restrict__ out) {
    int row = blockIdx.x;
    int t = threadIdx.x;
    float4 fa = ((const float4*)(g_y  + (size_t)row * HDIM))[t];
    float4 fb = ((const float4*)(g_y2 + (size_t)row * HDIM))[t];
    float4 bi = ((const float4*)b2)[t];
    float4 f;
    f.x = fa.x + fb.x + bi.x;
    f.y = fa.y + fb.y + bi.y;
    f.z = fa.z + fb.z + bi.z;
    f.w = fa.w + fb.w + bi.w;
    float s  = f.x + f.y + f.z + f.w;
    float sq = f.x*f.x + f.y*f.y + f.z*f.z + f.w*f.w;
    #pragma unroll
    for (int o = 16; o; o >>= 1) {
        s  += __shfl_xor_sync(0xffffffffu, s,  o);
        sq += __shfl_xor_sync(0xffffffffu, sq, o);
    }
    __shared__ float ss[8], ssq[8];
    int wid = t >> 5, lid = t & 31;
    if (lid == 0) { ss[wid] = s; ssq[wid] = sq; }
    __syncthreads();
    if (wid == 0) {
        s  = (lid < 8) ? ss[lid]  : 0.0f;
        sq = (lid < 8) ? ssq[lid] : 0.0f;
        #pragma unroll
        for (int o = 4; o; o >>= 1) {
            s  += __shfl_xor_sync(0xffffffffu, s,  o);
            sq += __shfl_xor_sync(0xffffffffu, sq, o);
        }
        if (lid == 0) { ss[0] = s; ssq[0] = sq; }
    }
    __syncthreads();
    float mu  = ss[0] * (1.0f / HDIM);
    float var = ssq[0] * (1.0f / HDIM) - mu * mu;
    float rs  = rsqrtf(var + 1e-5f);
    float4 wv = ((const float4*)w)[t];
    float4 bv = ((const float4*)b)[t];
    float4 xv = ((const float4*)(x + (size_t)row * HDIM))[t];
    float4 o;
    o.x = (f.x - mu) * rs * wv.x + bv.x + xv.x;
    o.y = (f.y - mu) * rs * wv.y + bv.y + xv.y;
    o.z = (f.z - mu) * rs * wv.z + bv.z + xv.z;
    o.w = (f.w - mu) * rs * wv.w + bv.w + xv.w;
    ((float4*)(out + (size_t)row * HDIM))[t] = o;
}

// ========================= mma.sync GEMM kernels =========================
// smem tiles: rows of 128 bytes (32 tf32), SW128-swizzled:
//   addr(row, kbyte) = base + row*128 + (kbyte ^ ((row & 7) << 4))

// ---- gemm1: ONE 512-thread CTA per SM.  CTA tile 128 x (128 gate + 128 lin).
// 16 warps as 4(wm: 32 rows) x 4(wn: 32 gate cols + 32 lin cols).
// Per-thread: 64 acc regs + light frags -> fits the 128-reg cap with slack.
// 3 stages x (A 16K + B 32K) = 144 KB smem.  Tensor 2048 cyc vs smem ~1875: slack.
#define G1_OFF_A(s)   ((s) * 16384)
#define G1_OFF_B(s)   (49152 + (s) * 32768)
#define G1_SMEM       147456

// gemm2 (R10 config + split-K): 4 stages x (A 16K + B 8K) = 96 KB
#define G2_OFF_A(s)   ((s) * 16384)
#define G2_OFF_B(s)   (65536 + (s) * 8192)
#define G2_SMEM       98304

// -------------------- GEMM1: g_xln @ W1^T -> GEGLU -> g_hid --------------------
__global__ __launch_bounds__(512, 1)
void gemm1_mma_kernel(const float* __restrict__ bias) {
    extern __shared__ char smem[];
    const uint32_t sb = smem_u32(smem);
    const int tid  = threadIdx.x;
    const int warp = tid >> 5, lane = tid & 31;
    const int wm = (warp & 3) * 32;       // 4 row groups of 32
    const int wn = (warp >> 2) * 32;      // 4 col groups of 32 (gate; lin at +128 B-rows)

    const int row0  = blockIdx.x * 128;   // m fastest (W1 tile L2-resident)
    const int colg0 = blockIdx.y * 128;

    const int a_rowf = (lane & 7) + ((lane >> 3) & 1) * 8;
    const int a_k16  = (lane >> 4) * 16;
    const int b_rowf = (lane & 7) + (lane >> 4) * 8;
    const int b_k16  = ((lane >> 3) & 1) * 16;

    float accg[2][4][4], accl[2][4][4];
    #pragma unroll
    for (int i = 0; i < 2; i++)
        #pragma unroll
        for (int j = 0; j < 4; j++)
            #pragma unroll
            for (int k = 0; k < 4; k++) { accg[i][j][k] = 0.f; accl[i][j][k] = 0.f; }

    const float* A = g_xln;
    const float* W = g_w1r;

    auto load_tile = [&](int t, int s) {
        const int k0 = t * 32;
        const uint32_t ab = sb + G1_OFF_A(s);
        const uint32_t bb = sb + G1_OFF_B(s);
        #pragma unroll
        for (int i = 0; i < 2; i++) {               // A: 128 rows x 8 chunks / 512 thr
            int idx = tid + i * 512;
            int r = idx >> 3, c = idx & 7;
            cp_async16(ab + r * 128 + ((c * 16) ^ ((r & 7) << 4)),
                       A + (size_t)(row0 + r) * HDIM + k0 + c * 4);
        }
        #pragma unroll
        for (int i = 0; i < 4; i++) {               // B: 256 rows (128 gate + 128 lin)
            int idx = tid + i * 512;
            int r = idx >> 3, c = idx & 7;
            size_t grow = (r < 128) ? (size_t)(colg0 + r)
                                    : (size_t)(IDIM + colg0 + r - 128);
            cp_async16(bb + r * 128 + ((c * 16) ^ ((r & 7) << 4)),
                       W + grow * HDIM + k0 + c * 4);
        }
        CP_COMMIT();
    };

    load_tile(0, 0);
    load_tile(1, 1);

    const int NT = HDIM / 32;  // 32
    int sidx = 0;              // t % 3
    for (int t = 0; t < NT; t++) {
        if (t + 1 < NT) CP_WAIT1(); else CP_WAIT0();
        __syncthreads();
        if (t + 2 < NT) load_tile(t + 2, (sidx + 2 >= 3) ? sidx - 1 : sidx + 2);
        const uint32_t ab = sb + G1_OFF_A(sidx);
        const uint32_t bb = sb + G1_OFF_B(sidx);
        #pragma unroll
        for (int ks = 0; ks < 4; ks++) {
            const int kbA = ks * 32 + a_k16;
            const int kbB = ks * 32 + b_k16;
            uint32_t aA[8], bG[8], bL[8];
            #pragma unroll
            for (int j = 0; j < 2; j++) {
                int ar = wm + j * 16 + a_rowf;
                ldsm4(aA + j * 4, ab + ar * 128 + (kbA ^ ((ar & 7) << 4)));
            }
            #pragma unroll
            for (int j = 0; j < 2; j++) {
                int gr = wn + j * 16 + b_rowf;
                ldsm4(bG + j * 4, bb + gr * 128 + (kbB ^ ((gr & 7) << 4)));
                int lr = 128 + wn + j * 16 + b_rowf;
                ldsm4(bL + j * 4, bb + lr * 128 + (kbB ^ ((lr & 7) << 4)));
            }
            #pragma unroll
            for (int j = 0; j < 2; j++) {
                mma_tf32(accg[j][0], aA + j * 4, bG[0], bG[1]);
                mma_tf32(accg[j][1], aA + j * 4, bG[2], bG[3]);
                mma_tf32(accg[j][2], aA + j * 4, bG[4], bG[5]);
                mma_tf32(accg[j][3], aA + j * 4, bG[6], bG[7]);
                mma_tf32(accl[j][0], aA + j * 4, bL[0], bL[1]);
                mma_tf32(accl[j][1], aA + j * 4, bL[2], bL[3]);
                mma_tf32(accl[j][2], aA + j * 4, bL[4], bL[5]);
                mma_tf32(accl[j][3], aA + j * 4, bL[6], bL[7]);
            }
        }
        sidx = (sidx + 1 >= 3) ? 0 : sidx + 1;
    }

    // epilogue: bias + GEGLU (round to tf32 so gemm2 can consume raw bits)
    #pragma unroll
    for (int mt = 0; mt < 2; mt++) {
        #pragma unroll
        for (int nt = 0; nt < 4; nt++) {
            int r = row0 + wm + mt * 16 + (lane >> 2);
            int c = colg0 + wn + nt * 8 + (lane & 3) * 2;
            float bg0 = __ldg(bias + c), bg1 = __ldg(bias + c + 1);
            float bl0 = __ldg(bias + IDIM + c), bl1 = __ldg(bias + IDIM + c + 1);
            float2 h0, h1;
            h0.x = roundtf(gelu_tanh(accg[mt][nt][0] + bg0) * (accl[mt][nt][0] + bl0));
            h0.y = roundtf(gelu_tanh(accg[mt][nt][1] + bg1) * (accl[mt][nt][1] + bl1));
            h1.x = roundtf(gelu_tanh(accg[mt][nt][2] + bg0) * (accl[mt][nt][2] + bl0));
            h1.y = roundtf(gelu_tanh(accg[mt][nt][3] + bg1) * (accl[mt][nt][3] + bl1));
            *(float2*)(g_hid + (size_t)r * IDIM + c)       = h0;
            *(float2*)(g_hid + (size_t)(r + 8) * IDIM + c) = h1;
        }
    }
}

// -------------------- GEMM2: g_hid @ W2^T -> g_y / g_y2 (split-K) --------------------
// 8 warps as 4(wm)x2(wn); warp tile 32x32.  blockIdx.z selects K-half.
__global__ __launch_bounds__(256, 2)
void gemm2_mma_kernel() {
    extern __shared__ char smem[];
    const uint32_t sb = smem_u32(smem);
    const int tid  = threadIdx.x;
    const int warp = tid >> 5, lane = tid & 31;
    const int wm = (warp & 3) * 32;
    const int wn = (warp >> 2) * 32;

    const int col0  = blockIdx.x * 64;   // n fastest: g_hid row-chunk reused across 16 CTAs
    const int row0  = blockIdx.y * 128;
    const int kbase = blockIdx.z * (IDIM / 2);
    float* OUT = blockIdx.z ? g_y2 : g_y;

    const int a_rowf = (lane & 7) + ((lane >> 3) & 1) * 8;
    const int a_k16  = (lane >> 4) * 16;
    const int b_rowf = (lane & 7) + (lane >> 4) * 8;
    const int b_k16  = ((lane >> 3) & 1) * 16;

    float acc[2][4][4];
    #pragma unroll
    for (int i = 0; i < 2; i++)
        #pragma unroll
        for (int j = 0; j < 4; j++)
            #pragma unroll
            for (int k = 0; k < 4; k++) acc[i][j][k] = 0.f;

    const float* A = g_hid;
    const float* W = g_w2r;

    auto load_tile = [&](int t, int s) {
        const int k0 = kbase + t * 32;
        const uint32_t ab = sb + G2_OFF_A(s);
        const uint32_t bb = sb + G2_OFF_B(s);
        #pragma unroll
        for (int i = 0; i < 4; i++) {
            int idx = tid + i * 256;
            int r = idx >> 3, c = idx & 7;
            cp_async16(ab + r * 128 + ((c * 16) ^ ((r & 7) << 4)),
                       A + (size_t)(row0 + r) * IDIM + k0 + c * 4);
        }
        #pragma unroll
        for (int i = 0; i < 2; i++) {
            int idx = tid + i * 256;
            int r = idx >> 3, c = idx & 7;
            cp_async16(bb + r * 128 + ((c * 16) ^ ((r & 7) << 4)),
                       W + (size_t)(col0 + r) * IDIM + k0 + c * 4);
        }
        CP_COMMIT();
    };

    load_tile(0, 0);
    load_tile(1, 1);
    load_tile(2, 2);

    const int NT = IDIM / 2 / 32;  // 64
    int sidx = 0;                  // t % 4
    for (int t = 0; t < NT; t++) {
        if (t + 2 < NT) CP_WAIT2();
        else if (t + 1 < NT) CP_WAIT1();
        else CP_WAIT0();
        __syncthreads();
        if (t + 3 < NT) load_tile(t + 3, (sidx + 3) & 3);
        const uint32_t ab = sb + G2_OFF_A(sidx);
        const uint32_t bb = sb + G2_OFF_B(sidx);

        uint32_t aA[2][8], bB[2][8];
        auto ldA = [&](uint32_t* d, int ks) {
            const int kb = ks * 32 + a_k16;
            #pragma unroll
            for (int j = 0; j < 2; j++) {
                int ar = wm + j * 16 + a_rowf;
                ldsm4(d + j * 4, ab + ar * 128 + (kb ^ ((ar & 7) << 4)));
            }
        };
        auto ldB = [&](uint32_t* d, int ks) {
            const int kb = ks * 32 + b_k16;
            #pragma unroll
            for (int j = 0; j < 2; j++) {
                int br = wn + j * 16 + b_rowf;
                ldsm4(d + j * 4, bb + br * 128 + (kb ^ ((br & 7) << 4)));
            }
        };

        ldA(aA[0], 0);
        ldB(bB[0], 0);
        #pragma unroll
        for (int ks = 0; ks < 4; ks++) {
            if (ks < 3) { ldA(aA[(ks + 1) & 1], ks + 1); ldB(bB[(ks + 1) & 1], ks + 1); }
            #pragma unroll
            for (int j = 0; j < 2; j++) {
                mma_tf32(acc[j][0], aA[ks & 1] + j * 4, bB[ks & 1][0], bB[ks & 1][1]);
                mma_tf32(acc[j][1], aA[ks & 1] + j * 4, bB[ks & 1][2], bB[ks & 1][3]);
                mma_tf32(acc[j][2], aA[ks & 1] + j * 4, bB[ks & 1][4], bB[ks & 1][5]);
                mma_tf32(acc[j][3], aA[ks & 1] + j * 4, bB[ks & 1][6], bB[ks & 1][7]);
            }
        }
        sidx = (sidx + 1) & 3;
    }

    #pragma unroll
    for (int mt = 0; mt < 2; mt++) {
        #pragma unroll
        for (int nt = 0; nt < 4; nt++) {
            int r = row0 + wm + mt * 16 + (lane >> 2);
            int c = col0 + wn + nt * 8 + (lane & 3) * 2;
            float2 y0, y1;
            y0.x = acc[mt][nt][0];
            y0.y = acc[mt][nt][1];
            y1.x = acc[mt][nt][2];
            y1.y = acc[mt][nt][3];
            *(float2*)(OUT + (size_t)r * HDIM + c)       = y0;
            *(float2*)(OUT + (size_t)(r + 8) * HDIM + c) = y1;
        }
    }
}

// =============================== launch ===============================
extern "C" void kernel_launch(void* const* d_in, const int* in_sizes, int n_in,
                              void* d_out, int out_size) {
    const float* x    = (const float*)d_in[0];
    const float* lnw  = (const float*)d_in[1];
    const float* lnb  = (const float*)d_in[2];
    const float* w1   = (const float*)d_in[3];
    const float* b1   = (const float*)d_in[4];
    const float* w2   = (const float*)d_in[5];
    const float* b2   = (const float*)d_in[6];
    const float* plnw = (const float*)d_in[7];
    const float* plnb = (const float*)d_in[8];
    float* out = (float*)d_out;

    cudaFuncSetAttribute(gemm1_mma_kernel,
                         cudaFuncAttributeMaxDynamicSharedMemorySize, G1_SMEM);
    cudaFuncSetAttribute(gemm2_mma_kernel,
                         cudaFuncAttributeMaxDynamicSharedMemorySize, G2_SMEM);

    float* w1r_p; cudaGetSymbolAddress((void**)&w1r_p, g_w1r);
    float* w2r_p; cudaGetSymbolAddress((void**)&w2r_p, g_w2r);

    // pre-round weights to tf32 (rna): mainloop then consumes raw bits, zero CVTs
    round_tf32_kernel<<<2 * IDIM * HDIM / 4 / 256, 256>>>(w1, w1r_p, 2 * IDIM * HDIM / 4);
    round_tf32_kernel<<<HDIM * IDIM / 4 / 256, 256>>>(w2, w2r_p, HDIM * IDIM / 4);

    ln_pre_kernel<<<N_TOK, 256>>>(x, lnw, lnb);
    gemm1_mma_kernel<<<dim3(64, 32), 512, G1_SMEM>>>(b1);
    gemm2_mma_kernel<<<dim3(16, 64, 2), 256, G2_SMEM>>>();
    ln_post_kernel<<<N_TOK, 256>>>(b2, plnw, plnb, x, out);
}

// round 15
// speedup vs baseline: 1.0819x; 1.0819x over previous
#include <cuda_runtime.h>
#include <cstdint>
#include <math.h>

// Problem shapes (fixed by the dataset instance)
#define N_TOK 8192
#define HDIM  1024
#define IDIM  4096

// -------- scratch (static __device__ arrays: allocation-free) --------
__device__ float g_xln[(size_t)N_TOK * HDIM];    //  32 MB (tf32-rounded LN output)
__device__ float g_hid[(size_t)N_TOK * IDIM];    // 128 MB (tf32-rounded GEGLU output)
__device__ float g_y  [(size_t)N_TOK * HDIM];    //  32 MB
__device__ float g_w1r[(size_t)2 * IDIM * HDIM]; //  64 MB (tf32-rounded W1)
__device__ float g_w2r[(size_t)HDIM * IDIM];     //  16 MB (tf32-rounded W2)

// ============================= helpers =============================
__device__ __forceinline__ uint32_t f2tf(float f) {
    uint32_t r;
    asm("cvt.rna.tf32.f32 %0, %1;" : "=r"(r) : "f"(f));
    return r;
}
__device__ __forceinline__ float roundtf(float f) { return __uint_as_float(f2tf(f)); }

__device__ __forceinline__ uint32_t smem_u32(const void* p) {
    uint32_t a;
    asm("{ .reg .u64 t; cvta.to.shared.u64 t, %1; cvt.u32.u64 %0, t; }" : "=r"(a) : "l"(p));
    return a;
}
__device__ __forceinline__ void cp_async16(uint32_t smem_addr, const void* gmem) {
    asm volatile("cp.async.cg.shared.global [%0], [%1], 16;\n" :: "r"(smem_addr), "l"(gmem));
}
#define CP_COMMIT() asm volatile("cp.async.commit_group;\n" ::)
#define CP_WAIT2()  asm volatile("cp.async.wait_group 2;\n" ::)
#define CP_WAIT1()  asm volatile("cp.async.wait_group 1;\n" ::)
#define CP_WAIT0()  asm volatile("cp.async.wait_group 0;\n" ::)

// ldmatrix x4: four 8x8 b16 tiles == four 8x4 tf32 tiles
__device__ __forceinline__ void ldsm4(uint32_t r[4], uint32_t addr) {
    asm volatile("ldmatrix.sync.aligned.m8n8.x4.shared.b16 {%0,%1,%2,%3}, [%4];"
                 : "=r"(r[0]), "=r"(r[1]), "=r"(r[2]), "=r"(r[3]) : "r"(addr));
}

__device__ __forceinline__ void mma_tf32(float c[4], const uint32_t a[4], const uint32_t b0,
                                         const uint32_t b1) {
    asm volatile(
        "mma.sync.aligned.m16n8k8.row.col.f32.tf32.tf32.f32 "
        "{%0,%1,%2,%3}, {%4,%5,%6,%7}, {%8,%9}, {%0,%1,%2,%3};"
        : "+f"(c[0]), "+f"(c[1]), "+f"(c[2]), "+f"(c[3])
        : "r"(a[0]), "r"(a[1]), "r"(a[2]), "r"(a[3]), "r"(b0), "r"(b1));
}

// Fast tanh-GELU: gelu(v) = v / (1 + exp2(-2*log2(e)*u)),  u = c0*(v + c1*v^3).
// EX2.approx + RCP.approx (~1e-6 rel err, well under the 1e-3 budget).
__device__ __forceinline__ float gelu_tanh(float v) {
    const float c0 = 0.7978845608028654f;   // sqrt(2/pi)
    const float c1 = 0.044715f;
    const float n2log2e = -2.8853900817779268f;  // -2*log2(e)
    float u = c0 * (v + c1 * v * v * v);
    float e;
    asm("ex2.approx.f32 %0, %1;" : "=f"(e) : "f"(n2log2e * u));
    float r;
    asm("rcp.approx.f32 %0, %1;" : "=f"(r) : "f"(1.0f + e));
    return v * r;
}

// ============================ tiny kernels ============================
__global__ void round_tf32_kernel(const float* __restrict__ in,
                                  float* __restrict__ outp, int n4) {
    int i = blockIdx.x * blockDim.x + threadIdx.x;
    if (i < n4) {
        float4 v = ((const float4*)in)[i];
        v.x = roundtf(v.x); v.y = roundtf(v.y);
        v.z = roundtf(v.z); v.w = roundtf(v.w);
        ((float4*)outp)[i] = v;
    }
}

__global__ void ln_pre_kernel(const float* __restrict__ x,
                              const float* __restrict__ w,
                              const float* __restrict__ b) {
    int row = blockIdx.x;
    int t = threadIdx.x;
    const float4* xr = (const float4*)(x + (size_t)row * HDIM);
    float4 f = xr[t];
    float s  = f.x + f.y + f.z + f.w;
    float sq = f.x*f.x + f.y*f.y + f.z*f.z + f.w*f.w;
    #pragma unroll
    for (int o = 16; o; o >>= 1) {
        s  += __shfl_xor_sync(0xffffffffu, s,  o);
        sq += __shfl_xor_sync(0xffffffffu, sq, o);
    }
    __shared__ float ss[8], ssq[8];
    int wid = t >> 5, lid = t & 31;
    if (lid == 0) { ss[wid] = s; ssq[wid] = sq; }
    __syncthreads();
    if (wid == 0) {
        s  = (lid < 8) ? ss[lid]  : 0.0f;
        sq = (lid < 8) ? ssq[lid] : 0.0f;
        #pragma unroll
        for (int o = 4; o; o >>= 1) {
            s  += __shfl_xor_sync(0xffffffffu, s,  o);
            sq += __shfl_xor_sync(0xffffffffu, sq, o);
        }
        if (lid == 0) { ss[0] = s; ssq[0] = sq; }
    }
    __syncthreads();
    float mu  = ss[0] * (1.0f / HDIM);
    float var = ssq[0] * (1.0f / HDIM) - mu * mu;
    float rs  = rsqrtf(var + 1e-5f);
    float4 wv = ((const float4*)w)[t];
    float4 bv = ((const float4*)b)[t];
    float4 o;
    o.x = roundtf((f.x - mu) * rs * wv.x + bv.x);
    o.y = roundtf((f.y - mu) * rs * wv.y + bv.y);
    o.z = roundtf((f.z - mu) * rs * wv.z + bv.z);
    o.w = roundtf((f.w - mu) * rs * wv.w + bv.w);
    ((float4*)(g_xln + (size_t)row * HDIM))[t] = o;
}

__global__ void ln_post_kernel(const float* __restrict__ w,
                               const float* __restrict__ b,
                               const float* __restrict__ x,
                               float* __restrict__ out) {
    int row = blockIdx.x;
    int t = threadIdx.x;
    const float4* yr = (const float4*)(g_y + (size_t)row * HDIM);
    float4 f = yr[t];
    float s  = f.x + f.y + f.z + f.w;
    float sq = f.x*f.x + f.y*f.y + f.z*f.z + f.w*f.w;
    #pragma unroll
    for (int o = 16; o; o >>= 1) {
        s  += __shfl_xor_sync(0xffffffffu, s,  o);
        sq += __shfl_xor_sync(0xffffffffu, sq, o);
    }
    __shared__ float ss[8], ssq[8];
    int wid = t >> 5, lid = t & 31;
    if (lid == 0) { ss[wid] = s; ssq[wid] = sq; }
    __syncthreads();
    if (wid == 0) {
        s  = (lid < 8) ? ss[lid]  : 0.0f;
        sq = (lid < 8) ? ssq[lid] : 0.0f;
        #pragma unroll
        for (int o = 4; o; o >>= 1) {
            s  += __shfl_xor_sync(0xffffffffu, s,  o);
            sq += __shfl_xor_sync(0xffffffffu, sq, o);
        }
        if (lid == 0) { ss[0] = s; ssq[0] = sq; }
    }
    __syncthreads();
    float mu  = ss[0] * (1.0f / HDIM);
    float var = ssq[0] * (1.0f / HDIM) - mu * mu;
    float rs  = rsqrtf(var + 1e-5f);
    float4 wv = ((const float4*)w)[t];
    float4 bv = ((const float4*)b)[t];
    float4 xv = ((const float4*)(x + (size_t)row * HDIM))[t];
    float4 o;
    o.x = (f.x - mu) * rs * wv.x + bv.x + xv.x;
    o.y = (f.y - mu) * rs * wv.y + bv.y + xv.y;
    o.z = (f.z - mu) * rs * wv.z + bv.z + xv.z;
    o.w = (f.w - mu) * rs * wv.w + bv.w + xv.w;
    ((float4*)(out + (size_t)row * HDIM))[t] = o;
}

// ========================= mma.sync GEMM kernels =========================
// smem tiles: rows of 128 bytes (32 tf32), SW128-swizzled:
//   addr(row, kbyte) = base + row*128 + (kbyte ^ ((row & 7) << 4))
// Fragment-level software pipelining (R10 config — measured best; FROZEN).

// gemm1: 3 stages x (A 16K + Bg 8K + Bl 8K) = 96 KB
#define G1_OFF_A(s)   ((s) * 16384)
#define G1_OFF_BG(s)  (49152 + (s) * 8192)
#define G1_OFF_BL(s)  (73728 + (s) * 8192)
#define G1_SMEM       98304

// gemm2: 4 stages x (A 16K + B 8K) = 96 KB
#define G2_OFF_A(s)   ((s) * 16384)
#define G2_OFF_B(s)   (65536 + (s) * 8192)
#define G2_SMEM       98304

// -------------------- GEMM1: g_xln @ W1^T -> GEGLU -> g_hid --------------------
// 8 warps as 2(wm)x4(wn); warp tile 64x16 over gate AND lin.
__global__ __launch_bounds__(256, 2)
void gemm1_mma_kernel(const float* __restrict__ bias) {
    extern __shared__ char smem[];
    const uint32_t sb = smem_u32(smem);
    const int tid  = threadIdx.x;
    const int warp = tid >> 5, lane = tid & 31;
    const int wm = (warp & 1) * 64;
    const int wn = (warp >> 1) * 16;

    const int row0 = blockIdx.x * 128;
    const int col0 = blockIdx.y * 64;

    const int a_rowf = (lane & 7) + ((lane >> 3) & 1) * 8;
    const int a_k16  = (lane >> 4) * 16;
    const int b_rowf = (lane & 7) + (lane >> 4) * 8;
    const int b_k16  = ((lane >> 3) & 1) * 16;

    float accg[4][2][4], accl[4][2][4];
    #pragma unroll
    for (int i = 0; i < 4; i++)
        #pragma unroll
        for (int j = 0; j < 2; j++)
            #pragma unroll
            for (int k = 0; k < 4; k++) { accg[i][j][k] = 0.f; accl[i][j][k] = 0.f; }

    const float* A = g_xln;
    const float* W = g_w1r;

    auto load_tile = [&](int t, int s) {
        const int k0 = t * 32;
        const uint32_t ab = sb + G1_OFF_A(s);
        const uint32_t bg = sb + G1_OFF_BG(s);
        const uint32_t bl = sb + G1_OFF_BL(s);
        #pragma unroll
        for (int i = 0; i < 4; i++) {
            int idx = tid + i * 256;
            int r = idx >> 3, c = idx & 7;
            cp_async16(ab + r * 128 + ((c * 16) ^ ((r & 7) << 4)),
                       A + (size_t)(row0 + r) * HDIM + k0 + c * 4);
        }
        #pragma unroll
        for (int i = 0; i < 2; i++) {
            int idx = tid + i * 256;
            int r = idx >> 3, c = idx & 7;
            uint32_t so = r * 128 + ((c * 16) ^ ((r & 7) << 4));
            cp_async16(bg + so, W + (size_t)(col0 + r) * HDIM + k0 + c * 4);
            cp_async16(bl + so, W + (size_t)(IDIM + col0 + r) * HDIM + k0 + c * 4);
        }
        CP_COMMIT();
    };

    load_tile(0, 0);
    load_tile(1, 1);

    const int NT = HDIM / 32;  // 32
    int sidx = 0;              // t % 3
    for (int t = 0; t < NT; t++) {
        if (t + 1 < NT) CP_WAIT1(); else CP_WAIT0();
        __syncthreads();
        if (t + 2 < NT) load_tile(t + 2, (sidx + 2 >= 3) ? sidx - 1 : sidx + 2);
        const uint32_t ab = sb + G1_OFF_A(sidx);
        const uint32_t bg = sb + G1_OFF_BG(sidx);
        const uint32_t bl = sb + G1_OFF_BL(sidx);

        uint32_t aA[2][8], bG[2][4], bL[2][4];
        auto ldA = [&](uint32_t* d, int ks, int h) {
            const int kb = ks * 32 + a_k16;
            #pragma unroll
            for (int j = 0; j < 2; j++) {
                int ar = wm + (2 * h + j) * 16 + a_rowf;
                ldsm4(d + j * 4, ab + ar * 128 + (kb ^ ((ar & 7) << 4)));
            }
        };
        auto ldB = [&](uint32_t* dg, uint32_t* dl, int ks) {
            const int br = wn + b_rowf;
            const uint32_t so = br * 128 + ((ks * 32 + b_k16) ^ ((br & 7) << 4));
            ldsm4(dg, bg + so);
            ldsm4(dl, bl + so);
        };

        ldA(aA[0], 0, 0);
        ldB(bG[0], bL[0], 0);
        #pragma unroll
        for (int s = 0; s < 8; s++) {
            const int ks = s >> 1, h = s & 1;
            if (s < 7) ldA(aA[(s + 1) & 1], (s + 1) >> 1, (s + 1) & 1);
            if (h == 0 && ks < 3) ldB(bG[(ks + 1) & 1], bL[(ks + 1) & 1], ks + 1);
            #pragma unroll
            for (int j = 0; j < 2; j++) {
                const int mt = 2 * h + j;
                mma_tf32(accg[mt][0], aA[s & 1] + j * 4, bG[ks & 1][0], bG[ks & 1][1]);
                mma_tf32(accg[mt][1], aA[s & 1] + j * 4, bG[ks & 1][2], bG[ks & 1][3]);
                mma_tf32(accl[mt][0], aA[s & 1] + j * 4, bL[ks & 1][0], bL[ks & 1][1]);
                mma_tf32(accl[mt][1], aA[s & 1] + j * 4, bL[ks & 1][2], bL[ks & 1][3]);
            }
        }
        sidx = (sidx + 1 >= 3) ? 0 : sidx + 1;
    }

    // epilogue: bias + fast GEGLU (round to tf32 so gemm2 can consume raw bits)
    #pragma unroll
    for (int mt = 0; mt < 4; mt++) {
        #pragma unroll
        for (int nt = 0; nt < 2; nt++) {
            int r = row0 + wm + mt * 16 + (lane >> 2);
            int c = col0 + wn + nt * 8 + (lane & 3) * 2;
            float bg0 = __ldg(bias + c), bg1 = __ldg(bias + c + 1);
            float bl0 = __ldg(bias + IDIM + c), bl1 = __ldg(bias + IDIM + c + 1);
            float2 h0, h1;
            h0.x = roundtf(gelu_tanh(accg[mt][nt][0] + bg0) * (accl[mt][nt][0] + bl0));
            h0.y = roundtf(gelu_tanh(accg[mt][nt][1] + bg1) * (accl[mt][nt][1] + bl1));
            h1.x = roundtf(gelu_tanh(accg[mt][nt][2] + bg0) * (accl[mt][nt][2] + bl0));
            h1.y = roundtf(gelu_tanh(accg[mt][nt][3] + bg1) * (accl[mt][nt][3] + bl1));
            *(float2*)(g_hid + (size_t)r * IDIM + c)       = h0;
            *(float2*)(g_hid + (size_t)(r + 8) * IDIM + c) = h1;
        }
    }
}

// -------------------- GEMM2: g_hid @ W2^T + b2 -> g_y --------------------
// 8 warps as 4(wm)x2(wn); warp tile 32x32 (R10 config — measured ~90% tensor).
__global__ __launch_bounds__(256, 2)
void gemm2_mma_kernel(const float* __restrict__ bias) {
    extern __shared__ char smem[];
    const uint32_t sb = smem_u32(smem);
    const int tid  = threadIdx.x;
    const int warp = tid >> 5, lane = tid & 31;
    const int wm = (warp & 3) * 32;
    const int wn = (warp >> 2) * 32;

    const int col0 = blockIdx.x * 64;
    const int row0 = blockIdx.y * 128;

    const int a_rowf = (lane & 7) + ((lane >> 3) & 1) * 8;
    const int a_k16  = (lane >> 4) * 16;
    const int b_rowf = (lane & 7) + (lane >> 4) * 8;
    const int b_k16  = ((lane >> 3) & 1) * 16;

    float acc[2][4][4];
    #pragma unroll
    for (int i = 0; i < 2; i++)
        #pragma unroll
        for (int j = 0; j < 4; j++)
            #pragma unroll
            for (int k = 0; k < 4; k++) acc[i][j][k] = 0.f;

    const float* A = g_hid;
    const float* W = g_w2r;

    auto load_tile = [&](int t, int s) {
        const int k0 = t * 32;
        const uint32_t ab = sb + G2_OFF_A(s);
        const uint32_t bb = sb + G2_OFF_B(s);
        #pragma unroll
        for (int i = 0; i < 4; i++) {
            int idx = tid + i * 256;
            int r = idx >> 3, c = idx & 7;
            cp_async16(ab + r * 128 + ((c * 16) ^ ((r & 7) << 4)),
                       A + (size_t)(row0 + r) * IDIM + k0 + c * 4);
        }
        #pragma unroll
        for (int i = 0; i < 2; i++) {
            int idx = tid + i * 256;
            int r = idx >> 3, c = idx & 7;
            cp_async16(bb + r * 128 + ((c * 16) ^ ((r & 7) << 4)),
                       W + (size_t)(col0 + r) * IDIM + k0 + c * 4);
        }
        CP_COMMIT();
    };

    load_tile(0, 0);
    load_tile(1, 1);
    load_tile(2, 2);

    const int NT = IDIM / 32;  // 128
    int sidx = 0;              // t % 4
    for (int t = 0; t < NT; t++) {
        if (t + 2 < NT) CP_WAIT2();
        else if (t + 1 < NT) CP_WAIT1();
        else CP_WAIT0();
        __syncthreads();
        if (t + 3 < NT) load_tile(t + 3, (sidx + 3) & 3);
        const uint32_t ab = sb + G2_OFF_A(sidx);
        const uint32_t bb = sb + G2_OFF_B(sidx);

        uint32_t aA[2][8], bB[2][8];
        auto ldA = [&](uint32_t* d, int ks) {
            const int kb = ks * 32 + a_k16;
            #pragma unroll
            for (int j = 0; j < 2; j++) {
                int ar = wm + j * 16 + a_rowf;
                ldsm4(d + j * 4, ab + ar * 128 + (kb ^ ((ar & 7) << 4)));
            }
        };
        auto ldB = [&](uint32_t* d, int ks) {
            const int kb = ks * 32 + b_k16;
            #pragma unroll
            for (int j = 0; j < 2; j++) {
                int br = wn + j * 16 + b_rowf;
                ldsm4(d + j * 4, bb + br * 128 + (kb ^ ((br & 7) << 4)));
            }
        };

        ldA(aA[0], 0);
        ldB(bB[0], 0);
        #pragma unroll
        for (int ks = 0; ks < 4; ks++) {
            if (ks < 3) { ldA(aA[(ks + 1) & 1], ks + 1); ldB(bB[(ks + 1) & 1], ks + 1); }
            #pragma unroll
            for (int j = 0; j < 2; j++) {
                mma_tf32(acc[j][0], aA[ks & 1] + j * 4, bB[ks & 1][0], bB[ks & 1][1]);
                mma_tf32(acc[j][1], aA[ks & 1] + j * 4, bB[ks & 1][2], bB[ks & 1][3]);
                mma_tf32(acc[j][2], aA[ks & 1] + j * 4, bB[ks & 1][4], bB[ks & 1][5]);
                mma_tf32(acc[j][3], aA[ks & 1] + j * 4, bB[ks & 1][6], bB[ks & 1][7]);
            }
        }
        sidx = (sidx + 1) & 3;
    }

    #pragma unroll
    for (int mt = 0; mt < 2; mt++) {
        #pragma unroll
        for (int nt = 0; nt < 4; nt++) {
            int r = row0 + wm + mt * 16 + (lane >> 2);
            int c = col0 + wn + nt * 8 + (lane & 3) * 2;
            float b0 = __ldg(bias + c), b1 = __ldg(bias + c + 1);
            float2 y0, y1;
            y0.x = acc[mt][nt][0] + b0;
            y0.y = acc[mt][nt][1] + b1;
            y1.x = acc[mt][nt][2] + b0;
            y1.y = acc[mt][nt][3] + b1;
            *(float2*)(g_y + (size_t)r * HDIM + c)       = y0;
            *(float2*)(g_y + (size_t)(r + 8) * HDIM + c) = y1;
        }
    }
}

// =============================== launch ===============================
extern "C" void kernel_launch(void* const* d_in, const int* in_sizes, int n_in,
                              void* d_out, int out_size) {
    const float* x    = (const float*)d_in[0];
    const float* lnw  = (const float*)d_in[1];
    const float* lnb  = (const float*)d_in[2];
    const float* w1   = (const float*)d_in[3];
    const float* b1   = (const float*)d_in[4];
    const float* w2   = (const float*)d_in[5];
    const float* b2   = (const float*)d_in[6];
    const float* plnw = (const float*)d_in[7];
    const float* plnb = (const float*)d_in[8];
    float* out = (float*)d_out;

    cudaFuncSetAttribute(gemm1_mma_kernel,
                         cudaFuncAttributeMaxDynamicSharedMemorySize, G1_SMEM);
    cudaFuncSetAttribute(gemm2_mma_kernel,
                         cudaFuncAttributeMaxDynamicSharedMemorySize, G2_SMEM);

    float* w1r_p; cudaGetSymbolAddress((void**)&w1r_p, g_w1r);
    float* w2r_p; cudaGetSymbolAddress((void**)&w2r_p, g_w2r);

    // pre-round weights to tf32 (rna): mainloop then consumes raw bits, zero CVTs
    round_tf32_kernel<<<2 * IDIM * HDIM / 4 / 256, 256>>>(w1, w1r_p, 2 * IDIM * HDIM / 4);
    round_tf32_kernel<<<HDIM * IDIM / 4 / 256, 256>>>(w2, w2r_p, HDIM * IDIM / 4);

    ln_pre_kernel<<<N_TOK, 256>>>(x, lnw, lnb);
    gemm1_mma_kernel<<<dim3(64, 64), 256, G1_SMEM>>>(b1);
    gemm2_mma_kernel<<<dim3(16, 64), 256, G2_SMEM>>>(b2);
    ln_post_kernel<<<N_TOK, 256>>>(plnw, plnb, x, out);
}